// round 12
// baseline (speedup 1.0000x reference)
#include <cuda_runtime.h>

// Slice_windows: (32,1,1024,1024) f32 -> (32,8) f32
//
// R11: R4 structure with 4x finer CTA granularity to kill the occupancy-
// quantization tail (512 CTAs @ occ4 = 3.46/SM -> ~15% makespan slack;
// 2048 small CTAs -> ~1.5%).
//  - One CTA per 128x128 tile (2048 CTAs, 256 threads).
//  - Gmem pass: 16 LDG.128/thread, barrier-free; k=2 + k=4 in registers.
//  - 32x32 k=4 sums -> smem; pyramid k=8..128 (tile = one k=128 window).
//  - Tile sums -> g_tile; k=256 = 2x2 tiles, done in fused finalize.
//  - Last-arriving CTA reduces partials in fixed order (deterministic).

#define NBATCH   32
#define NCTAS    2048           // 64 tiles/image (8x8 of 128x128)
#define NTHREADS 256
#define NLVL     7              // per-tile levels k=2..128

__device__ float g_parts[NLVL * NCTAS];  // SoA [level][tile]
__device__ float g_tile[NCTAS];          // per-tile total sum (one k=128 window)
__device__ int   g_count = 0;

__device__ __forceinline__ float plogp(float p) {
    // p * log2(p), 0 at p == 0
    return (p > 0.f) ? p * __log2f(p) : 0.f;
}
__device__ __forceinline__ float ent(float s, float inv_n) {
    const float p = s * inv_n;
    return plogp(p) + plogp(1.f - p);
}

// smem pyramid: 32^2 + 16^2 + 8^2 + 4^2 + 2^2 = 1364 floats
#define SMF 1364

__global__ void __launch_bounds__(NTHREADS, 4)
slice_windows(const float* __restrict__ x, float* __restrict__ out)
{
    __shared__ float sm[SMF];
    __shared__ float s_wp[8][NLVL];
    __shared__ bool  is_last;

    const int tid  = threadIdx.x;
    const int bid  = blockIdx.x;
    const int b    = bid >> 6;            // image
    const int loc  = bid & 63;            // tile within image
    const int row0 = (loc >> 3) * 128;
    const int col0 = (loc & 7) * 128;
    const float* __restrict__ img = x + (size_t)b * 1024 * 1024;

    float eacc[NLVL];
#pragma unroll
    for (int l = 0; l < NLVL; l++) eacc[l] = 0.f;

    // ---- Gmem pass: k=2 and k=4 in registers; 32x32 k=4 sums -> smem.
    {
        const int ox  = tid & 31;         // col-block (4 cols) 0..31
        const int oyb = tid >> 5;         // 0..7
        const float* base = img + (size_t)row0 * 1024 + col0 + ox * 4;
#pragma unroll 4
        for (int it = 0; it < 4; ++it) {
            const int orow4 = it * 8 + oyb;          // 4-row block 0..31
            const float* p = base + (size_t)orow4 * 4096;
            const float4 a0 = *(const float4*)(p);
            const float4 a1 = *(const float4*)(p + 1024);
            const float4 a2 = *(const float4*)(p + 2048);
            const float4 a3 = *(const float4*)(p + 3072);
            const float s00 = (a0.x + a0.y) + (a1.x + a1.y);
            const float s01 = (a0.z + a0.w) + (a1.z + a1.w);
            const float s10 = (a2.x + a2.y) + (a3.x + a3.y);
            const float s11 = (a2.z + a2.w) + (a3.z + a3.w);
            eacc[0] -= ent(s00, .25f) + ent(s01, .25f)
                     + ent(s10, .25f) + ent(s11, .25f);
            const float S = (s00 + s01) + (s10 + s11);
            eacc[1] -= ent(S, .0625f);
            sm[orow4 * 32 + ox] = S;
        }
    }
    __syncthreads();

    // ---- Pyramid in smem: l=2..6 (k=8..128), 32x32 -> 1x1.
    int in_off = 0, in_dim = 32, out_off = 1024;
#pragma unroll
    for (int l = 2; l < NLVL; l++) {
        const int out_dim = in_dim >> 1;
        const int nout = out_dim * out_dim;
        const float inv_n = 1.0f / (float)(1 << (2 * (l + 1)));  // 1/k^2
        if (tid < nout) {
            const int oy = tid / out_dim;
            const int ox = tid - oy * out_dim;
            const float* rp0 = sm + in_off + (2 * oy) * in_dim + 2 * ox;
            const float* rp1 = rp0 + in_dim;
            const float s = (rp0[0] + rp0[1]) + (rp1[0] + rp1[1]);
            eacc[l] -= ent(s, inv_n);
            if (l < NLVL - 1) sm[out_off + tid] = s;
            else              g_tile[bid] = s;      // tile total (k=128 window)
        }
        __syncthreads();
        in_off = out_off;
        in_dim = out_dim;
        out_off += nout;
    }

    // ---- Block-reduce the 7 per-thread entropy accumulators (8 warps)
    const int lane = tid & 31;
    const int warp = tid >> 5;
#pragma unroll
    for (int l = 0; l < NLVL; l++) {
        float v = eacc[l];
#pragma unroll
        for (int o = 16; o > 0; o >>= 1)
            v += __shfl_down_sync(0xffffffffu, v, o);
        if (lane == 0) s_wp[warp][l] = v;
    }
    __syncthreads();
    if (tid < NLVL) {
        float s = 0.f;
#pragma unroll
        for (int w = 0; w < 8; w++) s += s_wp[w][tid];
        g_parts[tid * NCTAS + bid] = s;
    }

    // ---- Fused finalize: last-arriving CTA computes the (32,8) output.
    __threadfence();
    if (tid == 0) {
        const int prev = atomicAdd(&g_count, 1);
        is_last = (prev == NCTAS - 1);
    }
    __syncthreads();
    if (is_last) {
        const int bb = tid >> 3;         // image 0..31
        const int l  = tid & 7;
        if (l < NLVL) {
            // levels k=2..128: sum this image's 64 contiguous tile partials
            const float* gp = g_parts + l * NCTAS + bb * 64;
            float s = 0.f;
#pragma unroll
            for (int t = 0; t < 64; t++) s += __ldcg(gp + t);
            const int d = 1024 >> (l + 1);   // windows per side
            out[bb * 8 + l] = s / (float)(d * d);
        } else {
            // k=256: 4x4 windows, each = 2x2 tiles of 128x128
            const float* tp = g_tile + bb * 64;
            float s = 0.f;
#pragma unroll
            for (int wy = 0; wy < 4; wy++)
#pragma unroll
                for (int wx = 0; wx < 4; wx++) {
                    const float S = __ldcg(tp + (2 * wy) * 8 + 2 * wx)
                                  + __ldcg(tp + (2 * wy) * 8 + 2 * wx + 1)
                                  + __ldcg(tp + (2 * wy + 1) * 8 + 2 * wx)
                                  + __ldcg(tp + (2 * wy + 1) * 8 + 2 * wx + 1);
                    s -= ent(S, 1.f / 65536.f);
                }
            out[bb * 8 + 7] = s / 16.f;
        }
        if (tid == 0) g_count = 0;           // reset for graph replay
    }
}

extern "C" void kernel_launch(void* const* d_in, const int* in_sizes, int n_in,
                              void* d_out, int out_size)
{
    (void)in_sizes; (void)n_in; (void)out_size;
    const float* x = (const float*)d_in[0];
    float* out = (float*)d_out;
    slice_windows<<<NCTAS, NTHREADS>>>(x, out);
}